// round 13
// baseline (speedup 1.0000x reference)
#include <cuda_runtime.h>
#include <cstddef>
#include <cstdint>

#define NUSER 100000
#define NITEM 100000
#define NEDGE 600000
#define NTOT  (NUSER + NITEM)
#define HDIM  128
#define LN_EPS 1e-5f

// ---------------- scratch (device globals; no allocation allowed) ----------------
__device__ __align__(128) float g_hu [(size_t)NUSER * HDIM];
__device__ __align__(128) float g_hi [(size_t)NITEM * HDIM];
__device__ __align__(128) float g_Mu [(size_t)NUSER * HDIM];
__device__ __align__(128) float g_Qu [(size_t)NUSER * HDIM];
__device__ __align__(128) float g_Mi [(size_t)NITEM * HDIM];
__device__ __align__(128) float g_Qi [(size_t)NITEM * HDIM];

__device__ int g_deg[NTOT];
__device__ int g_cur[NTOT];
__device__ int g_ptr[NTOT + 1];
__device__ int g_col[2 * NEDGE];
__device__ int g_bsum[256];
__device__ int g_boff[256];

#define SCAN_BLK 196

// ---------------- small helpers ----------------
__device__ __forceinline__ unsigned f2tf(float x) {
    unsigned r;
    asm("cvt.rna.tf32.f32 %0, %1;" : "=r"(r) : "f"(x));
    return r;
}
__device__ __forceinline__ void mma8(float* c, const unsigned* a, const unsigned* b) {
    asm volatile(
        "mma.sync.aligned.m16n8k8.row.col.f32.tf32.tf32.f32 "
        "{%0,%1,%2,%3}, {%4,%5,%6,%7}, {%8,%9}, {%0,%1,%2,%3};"
        : "+f"(c[0]), "+f"(c[1]), "+f"(c[2]), "+f"(c[3])
        : "r"(a[0]), "r"(a[1]), "r"(a[2]), "r"(a[3]), "r"(b[0]), "r"(b[1]));
}
__device__ __forceinline__ uint32_t smem_u32(const void* p) {
    uint32_t a;
    asm("{ .reg .u64 t; cvta.to.shared.u64 t, %1; cvt.u32.u64 %0, t; }" : "=r"(a) : "l"(p));
    return a;
}
__device__ __forceinline__ void cpa16(uint32_t dst, const void* src, int src_sz) {
    asm volatile("cp.async.cg.shared.global [%0], [%1], 16, %2;"
                 :: "r"(dst), "l"(src), "r"(src_sz));
}
__device__ __forceinline__ void cpa_commit() {
    asm volatile("cp.async.commit_group;" ::: "memory");
}
template<int N>
__device__ __forceinline__ void cpa_wait() {
    asm volatile("cp.async.wait_group %0;" :: "n"(N) : "memory");
}

// ---------------- CSR build ----------------
__global__ void zero_kernel(int* __restrict__ deg, int* __restrict__ cur) {
    int i = blockIdx.x * blockDim.x + threadIdx.x;
    if (i < NTOT) { deg[i] = 0; cur[i] = 0; }
}

__global__ void hist_kernel(const int* __restrict__ edge_ui, const int* __restrict__ edge_iu,
                            int* __restrict__ deg) {
    int i = blockIdx.x * blockDim.x + threadIdx.x;
    if (i < NEDGE) {
        atomicAdd(&deg[__ldg(edge_iu + NEDGE + i)], 1);
    } else if (i < 2 * NEDGE) {
        atomicAdd(&deg[NUSER + __ldg(edge_ui + NEDGE + (i - NEDGE))], 1);
    }
}

__global__ void scan1_kernel(const int* __restrict__ deg, int* __restrict__ bsum) {
    __shared__ int s[8];
    int b = blockIdx.x;
    int base = b * 1024 + threadIdx.x * 4;
    int sum = 0;
    if (base + 3 < NTOT) {
        int4 v = *reinterpret_cast<const int4*>(deg + base);
        sum = v.x + v.y + v.z + v.w;
    } else {
        for (int j = 0; j < 4; j++) if (base + j < NTOT) sum += deg[base + j];
    }
    #pragma unroll
    for (int o = 16; o; o >>= 1) sum += __shfl_xor_sync(0xffffffffu, sum, o);
    if ((threadIdx.x & 31) == 0) s[threadIdx.x >> 5] = sum;
    __syncthreads();
    if (threadIdx.x == 0) {
        int t = 0;
        #pragma unroll
        for (int j = 0; j < 8; j++) t += s[j];
        bsum[b] = t;
    }
}

__global__ void scan2_kernel(const int* __restrict__ bsum, int* __restrict__ boff,
                             int* __restrict__ ptr) {
    __shared__ int s[256];
    int t = threadIdx.x;
    int v = (t < SCAN_BLK) ? bsum[t] : 0;
    s[t] = v;
    __syncthreads();
    for (int off = 1; off < 256; off <<= 1) {
        int u = (t >= off) ? s[t - off] : 0;
        __syncthreads();
        s[t] += u;
        __syncthreads();
    }
    if (t < SCAN_BLK) boff[t] = s[t] - v;
    if (t == 0) ptr[NTOT] = 2 * NEDGE;
}

__global__ void scan3_kernel(const int* __restrict__ deg, const int* __restrict__ boff,
                             int* __restrict__ ptr) {
    __shared__ int ws[8];
    int b = blockIdx.x;
    int t = threadIdx.x;
    int lane = t & 31, w = t >> 5;
    int base = b * 1024 + t * 4;

    int d[4];
    #pragma unroll
    for (int j = 0; j < 4; j++) d[j] = (base + j < NTOT) ? deg[base + j] : 0;
    int tsum = d[0] + d[1] + d[2] + d[3];

    int incl = tsum;
    #pragma unroll
    for (int o = 1; o < 32; o <<= 1) {
        int u = __shfl_up_sync(0xffffffffu, incl, o);
        if (lane >= o) incl += u;
    }
    if (lane == 31) ws[w] = incl;
    __syncthreads();
    int wexcl = 0;
    #pragma unroll
    for (int j = 0; j < 8; j++) wexcl += (j < w) ? ws[j] : 0;
    int run = boff[b] + wexcl + (incl - tsum);
    #pragma unroll
    for (int j = 0; j < 4; j++) {
        if (base + j < NTOT) ptr[base + j] = run;
        run += d[j];
    }
}

__global__ void fill_kernel(const int* __restrict__ edge_ui, const int* __restrict__ edge_iu,
                            const int* __restrict__ ptr, int* __restrict__ cur,
                            int* __restrict__ col) {
    int i = blockIdx.x * blockDim.x + threadIdx.x;
    if (i < NEDGE) {
        int d = __ldg(edge_iu + NEDGE + i);
        int p = atomicAdd(&cur[d], 1);
        col[__ldg(ptr + d) + p] = __ldg(edge_iu + i);
    } else if (i < 2 * NEDGE) {
        int e = i - NEDGE;
        int d = NUSER + __ldg(edge_ui + NEDGE + e);
        int p = atomicAdd(&cur[d], 1);
        col[__ldg(ptr + d) + p] = __ldg(edge_ui + e);
    }
}

// ---------------- TF32 mma GEMM, cp.async 2-stage, concatenated N with split output --------
// C0[M,SPLIT] = A[M,K] @ W0[K,SPLIT]  (+bias,ReLU when BIASRELU)
// C1[M,BN-SPLIT] = A[M,K] @ W1[K,BN-SPLIT]            (only when SPLIT < BN)
// Tile: 128 x BN per CTA, 256 threads, 8 warps (2 in M x 4 in N), WM=64, WN=BN/4.
template<int BN, int SPLIT, bool BIASRELU>
__global__ void __launch_bounds__(256)
gemm_kernel(const float* __restrict__ A,
            const float* __restrict__ W0, const float* __restrict__ W1,
            const float* __restrict__ bias,
            float* __restrict__ C0, float* __restrict__ C1,
            int M, int K)
{
    constexpr int WN = BN / 4;
    constexpr int MT = 4;          // 64 / 16
    constexpr int NT = WN / 8;
    constexpr int BROW = BN + 8;   // Bs row stride (floats)
    constexpr int A_ST = 128 * 36; // floats per A stage
    constexpr int B_ST = 32 * BROW;
    constexpr int STG  = A_ST + B_ST;

    extern __shared__ float sm[];
    const uint32_t smb = smem_u32(sm);

    const int t = threadIdx.x;
    const int w = t >> 5, lane = t & 31;
    const int g = lane >> 2, tg = lane & 3;
    const int wm = w >> 2, wn = w & 3;
    const int m0 = blockIdx.x * 128;
    const int CH = K >> 5;

    float acc[MT][NT][4];
    #pragma unroll
    for (int mt = 0; mt < MT; mt++)
        #pragma unroll
        for (int nt = 0; nt < NT; nt++)
            #pragma unroll
            for (int j = 0; j < 4; j++) acc[mt][nt][j] = 0.f;

    // ---- async tile loaders ----
    auto loadA = [&](int c, int buf) {
        uint32_t base = smb + (uint32_t)(buf * STG) * 4u;
        #pragma unroll
        for (int q = 0; q < 4; q++) {
            int i = t + q * 256;          // 1024 16B-chunks
            int row = i >> 3, j = i & 7;
            bool val = (m0 + row) < M;
            const float* src = val ? (A + (size_t)(m0 + row) * K + c * 32 + j * 4) : A;
            cpa16(base + (uint32_t)(row * 36 + j * 4) * 4u, src, val ? 16 : 0);
        }
    };
    auto loadB = [&](int c, int buf) {
        uint32_t base = smb + (uint32_t)(buf * STG + A_ST) * 4u;
        #pragma unroll
        for (int i = t; i < 8 * BN; i += 256) {
            int k = i / (BN / 4);
            int ncol = (i % (BN / 4)) * 4;
            const float* src = (ncol < SPLIT)
                ? (W0 + (size_t)(c * 32 + k) * SPLIT + ncol)
                : (W1 + (size_t)(c * 32 + k) * (BN - SPLIT) + (ncol - SPLIT));
            cpa16(base + (uint32_t)(k * BROW + ncol) * 4u, src, 16);
        }
    };

    loadA(0, 0); loadB(0, 0); cpa_commit();

    for (int c = 0; c < CH; c++) {
        if (c + 1 < CH) {
            loadA(c + 1, (c + 1) & 1); loadB(c + 1, (c + 1) & 1); cpa_commit();
            cpa_wait<1>();
        } else {
            cpa_wait<0>();
        }
        __syncthreads();

        const float* As = sm + (c & 1) * STG;
        const float* Bs = As + A_ST;

        #pragma unroll
        for (int kk = 0; kk < 32; kk += 8) {
            unsigned a[MT][4], b[NT][2];
            #pragma unroll
            for (int mt = 0; mt < MT; mt++) {
                int r = wm * 64 + mt * 16 + g;
                a[mt][0] = f2tf(As[r * 36 + kk + tg]);
                a[mt][1] = f2tf(As[(r + 8) * 36 + kk + tg]);
                a[mt][2] = f2tf(As[r * 36 + kk + tg + 4]);
                a[mt][3] = f2tf(As[(r + 8) * 36 + kk + tg + 4]);
            }
            #pragma unroll
            for (int nt = 0; nt < NT; nt++) {
                int cc = wn * WN + nt * 8 + g;
                b[nt][0] = f2tf(Bs[(kk + tg) * BROW + cc]);
                b[nt][1] = f2tf(Bs[(kk + tg + 4) * BROW + cc]);
            }
            #pragma unroll
            for (int mt = 0; mt < MT; mt++)
                #pragma unroll
                for (int nt = 0; nt < NT; nt++)
                    mma8(acc[mt][nt], a[mt], b[nt]);
        }
        __syncthreads();
    }

    // ---- epilogue: split fragment stores ----
    #pragma unroll
    for (int mt = 0; mt < MT; mt++) {
        int r0 = m0 + wm * 64 + mt * 16 + g;
        #pragma unroll
        for (int nt = 0; nt < NT; nt++) {
            int c = wn * WN + nt * 8 + 2 * tg;
            float x0 = acc[mt][nt][0], x1 = acc[mt][nt][1];
            float x2 = acc[mt][nt][2], x3 = acc[mt][nt][3];
            if (BIASRELU) {
                float b0 = __ldg(bias + c), b1 = __ldg(bias + c + 1);
                x0 = fmaxf(x0 + b0, 0.f); x1 = fmaxf(x1 + b1, 0.f);
                x2 = fmaxf(x2 + b0, 0.f); x3 = fmaxf(x3 + b1, 0.f);
            }
            float* base; int stride, cc;
            if (c < SPLIT) { base = C0; stride = SPLIT; cc = c; }
            else           { base = C1; stride = BN - SPLIT; cc = c - SPLIT; }
            if (r0 < M)
                *reinterpret_cast<float2*>(base + (size_t)r0 * stride + cc) = make_float2(x0, x1);
            if (r0 + 8 < M)
                *reinterpret_cast<float2*>(base + (size_t)(r0 + 8) * stride + cc) = make_float2(x2, x3);
        }
    }
}

// ---------------- fused CSR gather-mean + self + bias + LN (+ReLU), x4 unrolled ----------------
template<int VPL, bool RELU>
__global__ void aggfin_kernel(const float* __restrict__ msg, const float* __restrict__ self,
                              const int* __restrict__ ptr, const int* __restrict__ col,
                              const float* __restrict__ bias,
                              const float* __restrict__ gamma, const float* __restrict__ beta,
                              float* __restrict__ out, int n)
{
    constexpr int C = 32 * VPL;
    int gw = (blockIdx.x * blockDim.x + threadIdx.x) >> 5;
    if (gw >= n) return;
    int lane = threadIdx.x & 31;

    int p0 = __ldg(ptr + gw), p1 = __ldg(ptr + gw + 1);
    float v[VPL];
    #pragma unroll
    for (int j = 0; j < VPL; j++) v[j] = 0.f;

    int e = p0;
    if (VPL == 4) {
        for (; e + 4 <= p1; e += 4) {
            int s0 = __ldg(col + e),     s1 = __ldg(col + e + 1);
            int s2 = __ldg(col + e + 2), s3 = __ldg(col + e + 3);
            float4 a = *reinterpret_cast<const float4*>(msg + (size_t)s0 * C + lane * 4);
            float4 b = *reinterpret_cast<const float4*>(msg + (size_t)s1 * C + lane * 4);
            float4 c = *reinterpret_cast<const float4*>(msg + (size_t)s2 * C + lane * 4);
            float4 d = *reinterpret_cast<const float4*>(msg + (size_t)s3 * C + lane * 4);
            v[0] += (a.x + b.x) + (c.x + d.x);
            v[1] += (a.y + b.y) + (c.y + d.y);
            v[2 % VPL] += (a.z + b.z) + (c.z + d.z);
            v[3 % VPL] += (a.w + b.w) + (c.w + d.w);
        }
        for (; e < p1; e++) {
            int s = __ldg(col + e);
            float4 a = *reinterpret_cast<const float4*>(msg + (size_t)s * C + lane * 4);
            v[0] += a.x; v[1] += a.y; v[2 % VPL] += a.z; v[3 % VPL] += a.w;
        }
    } else {
        for (; e + 4 <= p1; e += 4) {
            int s0 = __ldg(col + e),     s1 = __ldg(col + e + 1);
            int s2 = __ldg(col + e + 2), s3 = __ldg(col + e + 3);
            float2 a = *reinterpret_cast<const float2*>(msg + (size_t)s0 * C + lane * 2);
            float2 b = *reinterpret_cast<const float2*>(msg + (size_t)s1 * C + lane * 2);
            float2 c = *reinterpret_cast<const float2*>(msg + (size_t)s2 * C + lane * 2);
            float2 d = *reinterpret_cast<const float2*>(msg + (size_t)s3 * C + lane * 2);
            v[0] += (a.x + b.x) + (c.x + d.x);
            v[1 % VPL] += (a.y + b.y) + (c.y + d.y);
        }
        for (; e < p1; e++) {
            int s = __ldg(col + e);
            float2 a = *reinterpret_cast<const float2*>(msg + (size_t)s * C + lane * 2);
            v[0] += a.x; v[1 % VPL] += a.y;
        }
    }
    float inv = 1.f / fmaxf((float)(p1 - p0), 1.f);

    const float* sp = self + (size_t)gw * C + lane * VPL;
    if (VPL == 4) {
        float4 s4 = *reinterpret_cast<const float4*>(sp);
        v[0] = v[0] * inv + s4.x; v[1] = v[1] * inv + s4.y;
        v[2 % VPL] = v[2 % VPL] * inv + s4.z; v[3 % VPL] = v[3 % VPL] * inv + s4.w;
    } else {
        float2 s2 = *reinterpret_cast<const float2*>(sp);
        v[0] = v[0] * inv + s2.x; v[1 % VPL] = v[1 % VPL] * inv + s2.y;
    }
    #pragma unroll
    for (int j = 0; j < VPL; j++) v[j] += __ldg(bias + lane * VPL + j);

    float s = 0.f;
    #pragma unroll
    for (int j = 0; j < VPL; j++) s += v[j];
    #pragma unroll
    for (int o = 16; o > 0; o >>= 1) s += __shfl_xor_sync(0xffffffffu, s, o);
    float mean = s * (1.f / C);
    float q = 0.f;
    #pragma unroll
    for (int j = 0; j < VPL; j++) { float d = v[j] - mean; q += d * d; }
    #pragma unroll
    for (int o = 16; o > 0; o >>= 1) q += __shfl_xor_sync(0xffffffffu, q, o);
    float rstd = rsqrtf(q * (1.f / C) + LN_EPS);

    float* op = out + (size_t)gw * C + lane * VPL;
    float ov[VPL];
    #pragma unroll
    for (int j = 0; j < VPL; j++) {
        float x = (v[j] - mean) * rstd * __ldg(gamma + lane * VPL + j) + __ldg(beta + lane * VPL + j);
        ov[j] = RELU ? fmaxf(x, 0.f) : x;
    }
    if (VPL == 4)
        *reinterpret_cast<float4*>(op) = make_float4(ov[0], ov[1], ov[2 % VPL], ov[3 % VPL]);
    else
        *reinterpret_cast<float2*>(op) = make_float2(ov[0], ov[1 % VPL]);
}

// ---------------- host ----------------
extern "C" void kernel_launch(void* const* d_in, const int* in_sizes, int n_in,
                              void* d_out, int out_size) {
    (void)in_sizes; (void)n_in; (void)out_size;

    const float* x_user  = (const float*)d_in[0];
    const float* x_item  = (const float*)d_in[1];
    const int*   edge_ui = (const int*)d_in[2];
    const int*   edge_iu = (const int*)d_in[3];
    const float* Wp_u   = (const float*)d_in[4];
    const float* bp_u   = (const float*)d_in[5];
    const float* Wp_i   = (const float*)d_in[6];
    const float* bp_i   = (const float*)d_in[7];
    const float* Wl0_ui = (const float*)d_in[8];
    const float* bl0_ui = (const float*)d_in[9];
    const float* Wr0_ui = (const float*)d_in[10];
    const float* Wl0_iu = (const float*)d_in[11];
    const float* bl0_iu = (const float*)d_in[12];
    const float* Wr0_iu = (const float*)d_in[13];
    const float* g0_u   = (const float*)d_in[14];
    const float* b0_u   = (const float*)d_in[15];
    const float* g0_i   = (const float*)d_in[16];
    const float* b0_i   = (const float*)d_in[17];
    const float* Wl1_ui = (const float*)d_in[18];
    const float* bl1_ui = (const float*)d_in[19];
    const float* Wr1_ui = (const float*)d_in[20];
    const float* Wl1_iu = (const float*)d_in[21];
    const float* bl1_iu = (const float*)d_in[22];
    const float* Wr1_iu = (const float*)d_in[23];
    const float* g1_u   = (const float*)d_in[24];
    const float* b1_u   = (const float*)d_in[25];
    const float* g1_i   = (const float*)d_in[26];
    const float* b1_i   = (const float*)d_in[27];

    float* out = (float*)d_out;
    float* out_u = out;
    float* out_i = out + (size_t)NUSER * 64;

    float *hu, *hi, *Mu, *Qu, *Mi, *Qi;
    int *deg, *cur, *ptr, *col, *bsum, *boff;
    cudaGetSymbolAddress((void**)&hu, g_hu);
    cudaGetSymbolAddress((void**)&hi, g_hi);
    cudaGetSymbolAddress((void**)&Mu, g_Mu);
    cudaGetSymbolAddress((void**)&Qu, g_Qu);
    cudaGetSymbolAddress((void**)&Mi, g_Mi);
    cudaGetSymbolAddress((void**)&Qi, g_Qi);
    cudaGetSymbolAddress((void**)&deg, g_deg);
    cudaGetSymbolAddress((void**)&cur, g_cur);
    cudaGetSymbolAddress((void**)&ptr, g_ptr);
    cudaGetSymbolAddress((void**)&col, g_col);
    cudaGetSymbolAddress((void**)&bsum, g_bsum);
    cudaGetSymbolAddress((void**)&boff, g_boff);

    const int* ptr_u = ptr;
    const int* ptr_i = ptr + NUSER;

    // dynamic smem: 2 stages of (A: 128*36 + B: 32*(BN+8)) floats
    const int smem128 = 2 * (128 * 36 + 32 * (128 + 8)) * 4;   //  71680 B
    const int smem256 = 2 * (128 * 36 + 32 * (256 + 8)) * 4;   // 104448 B
    cudaFuncSetAttribute(gemm_kernel<128, 128, true>,  cudaFuncAttributeMaxDynamicSharedMemorySize, smem128);
    cudaFuncSetAttribute(gemm_kernel<256, 128, false>, cudaFuncAttributeMaxDynamicSharedMemorySize, smem256);
    cudaFuncSetAttribute(gemm_kernel<128, 64,  false>, cudaFuncAttributeMaxDynamicSharedMemorySize, smem128);

    const int e2g = (2 * NEDGE + 255) / 256;
    const int zg  = (NTOT + 255) / 256;
    const int gm  = (NUSER + 127) / 128;
    const int ag  = (NUSER * 32 + 255) / 256;

    // ---- CSR build ----
    zero_kernel<<<zg, 256>>>(deg, cur);
    hist_kernel<<<e2g, 256>>>(edge_ui, edge_iu, deg);
    scan1_kernel<<<SCAN_BLK, 256>>>(deg, bsum);
    scan2_kernel<<<1, 256>>>(bsum, boff, ptr);
    scan3_kernel<<<SCAN_BLK, 256>>>(deg, boff, ptr);
    fill_kernel<<<e2g, 256>>>(edge_ui, edge_iu, ptr, cur, col);

    // ---- input projections + ReLU ----
    gemm_kernel<128, 128, true><<<gm, 256, smem128>>>(x_user, Wp_u, Wp_u, bp_u, hu, hu, NUSER, 96);
    gemm_kernel<128, 128, true><<<gm, 256, smem128>>>(x_item, Wp_i, Wp_i, bp_i, hi, hi, NITEM, 160);

    // ---- layer 0: concatenated source-side GEMMs (N=256, split 128/128) ----
    gemm_kernel<256, 128, false><<<gm, 256, smem256>>>(hu, Wl0_ui, Wr0_iu, nullptr, Mu, Qu, NUSER, 128);
    gemm_kernel<256, 128, false><<<gm, 256, smem256>>>(hi, Wl0_iu, Wr0_ui, nullptr, Mi, Qi, NITEM, 128);

    aggfin_kernel<4, true><<<ag, 256>>>(Mu, Qi, ptr_i, col, bl0_ui, g0_i, b0_i, hi, NITEM);
    aggfin_kernel<4, true><<<ag, 256>>>(Mi, Qu, ptr_u, col, bl0_iu, g0_u, b0_u, hu, NUSER);

    // ---- layer 1: concatenated source-side GEMMs (N=128, split 64/64) ----
    gemm_kernel<128, 64, false><<<gm, 256, smem128>>>(hu, Wl1_ui, Wr1_iu, nullptr, Mu, Qu, NUSER, 128);
    gemm_kernel<128, 64, false><<<gm, 256, smem128>>>(hi, Wl1_iu, Wr1_ui, nullptr, Mi, Qi, NITEM, 128);

    aggfin_kernel<2, false><<<ag, 256>>>(Mu, Qi, ptr_i, col, bl1_ui, g1_i, b1_i, out_i, NITEM);
    aggfin_kernel<2, false><<<ag, 256>>>(Mi, Qu, ptr_u, col, bl1_iu, g1_u, b1_u, out_u, NUSER);
}

// round 14
// speedup vs baseline: 1.4788x; 1.4788x over previous
#include <cuda_runtime.h>
#include <cstddef>
#include <cstdint>

#define NUSER 100000
#define NITEM 100000
#define NEDGE 600000
#define NTOT  (NUSER + NITEM)
#define HDIM  128
#define LN_EPS 1e-5f

// ---------------- scratch (device globals; no allocation allowed) ----------------
__device__ __align__(128) float g_hu [(size_t)NUSER * HDIM];
__device__ __align__(128) float g_hi [(size_t)NITEM * HDIM];
__device__ __align__(128) float g_Mu [(size_t)NUSER * HDIM];
__device__ __align__(128) float g_Qu [(size_t)NUSER * HDIM];
__device__ __align__(128) float g_Mi [(size_t)NITEM * HDIM];
__device__ __align__(128) float g_Qi [(size_t)NITEM * HDIM];

__device__ int g_deg[NTOT];
__device__ int g_cur[NTOT];
__device__ int g_ptr[NTOT + 1];
__device__ int g_col[2 * NEDGE];
__device__ int g_bsum[256];
__device__ int g_boff[256];

#define SCAN_BLK 196

// ---------------- small helpers ----------------
__device__ __forceinline__ unsigned f2tf(float x) {
    unsigned r;
    asm("cvt.rna.tf32.f32 %0, %1;" : "=r"(r) : "f"(x));
    return r;
}
__device__ __forceinline__ void mma8(float* c, const unsigned* a, const unsigned* b) {
    asm volatile(
        "mma.sync.aligned.m16n8k8.row.col.f32.tf32.tf32.f32 "
        "{%0,%1,%2,%3}, {%4,%5,%6,%7}, {%8,%9}, {%0,%1,%2,%3};"
        : "+f"(c[0]), "+f"(c[1]), "+f"(c[2]), "+f"(c[3])
        : "r"(a[0]), "r"(a[1]), "r"(a[2]), "r"(a[3]), "r"(b[0]), "r"(b[1]));
}
__device__ __forceinline__ uint32_t smem_u32(const void* p) {
    uint32_t a;
    asm("{ .reg .u64 t; cvta.to.shared.u64 t, %1; cvt.u32.u64 %0, t; }" : "=r"(a) : "l"(p));
    return a;
}
__device__ __forceinline__ void cpa16(uint32_t dst, const void* src, int src_sz) {
    asm volatile("cp.async.cg.shared.global [%0], [%1], 16, %2;"
                 :: "r"(dst), "l"(src), "r"(src_sz));
}
__device__ __forceinline__ void cpa_commit() {
    asm volatile("cp.async.commit_group;" ::: "memory");
}
template<int N>
__device__ __forceinline__ void cpa_wait() {
    asm volatile("cp.async.wait_group %0;" :: "n"(N) : "memory");
}

// ---------------- CSR build ----------------
__global__ void zero_kernel(int* __restrict__ deg, int* __restrict__ cur) {
    int i = blockIdx.x * blockDim.x + threadIdx.x;
    if (i < NTOT) { deg[i] = 0; cur[i] = 0; }
}

__global__ void hist_kernel(const int* __restrict__ edge_ui, const int* __restrict__ edge_iu,
                            int* __restrict__ deg) {
    int i = blockIdx.x * blockDim.x + threadIdx.x;
    if (i < NEDGE) {
        atomicAdd(&deg[__ldg(edge_iu + NEDGE + i)], 1);
    } else if (i < 2 * NEDGE) {
        atomicAdd(&deg[NUSER + __ldg(edge_ui + NEDGE + (i - NEDGE))], 1);
    }
}

__global__ void scan1_kernel(const int* __restrict__ deg, int* __restrict__ bsum) {
    __shared__ int s[8];
    int b = blockIdx.x;
    int base = b * 1024 + threadIdx.x * 4;
    int sum = 0;
    if (base + 3 < NTOT) {
        int4 v = *reinterpret_cast<const int4*>(deg + base);
        sum = v.x + v.y + v.z + v.w;
    } else {
        for (int j = 0; j < 4; j++) if (base + j < NTOT) sum += deg[base + j];
    }
    #pragma unroll
    for (int o = 16; o; o >>= 1) sum += __shfl_xor_sync(0xffffffffu, sum, o);
    if ((threadIdx.x & 31) == 0) s[threadIdx.x >> 5] = sum;
    __syncthreads();
    if (threadIdx.x == 0) {
        int t = 0;
        #pragma unroll
        for (int j = 0; j < 8; j++) t += s[j];
        bsum[b] = t;
    }
}

__global__ void scan2_kernel(const int* __restrict__ bsum, int* __restrict__ boff,
                             int* __restrict__ ptr) {
    __shared__ int s[256];
    int t = threadIdx.x;
    int v = (t < SCAN_BLK) ? bsum[t] : 0;
    s[t] = v;
    __syncthreads();
    for (int off = 1; off < 256; off <<= 1) {
        int u = (t >= off) ? s[t - off] : 0;
        __syncthreads();
        s[t] += u;
        __syncthreads();
    }
    if (t < SCAN_BLK) boff[t] = s[t] - v;
    if (t == 0) ptr[NTOT] = 2 * NEDGE;
}

__global__ void scan3_kernel(const int* __restrict__ deg, const int* __restrict__ boff,
                             int* __restrict__ ptr) {
    __shared__ int ws[8];
    int b = blockIdx.x;
    int t = threadIdx.x;
    int lane = t & 31, w = t >> 5;
    int base = b * 1024 + t * 4;

    int d[4];
    #pragma unroll
    for (int j = 0; j < 4; j++) d[j] = (base + j < NTOT) ? deg[base + j] : 0;
    int tsum = d[0] + d[1] + d[2] + d[3];

    int incl = tsum;
    #pragma unroll
    for (int o = 1; o < 32; o <<= 1) {
        int u = __shfl_up_sync(0xffffffffu, incl, o);
        if (lane >= o) incl += u;
    }
    if (lane == 31) ws[w] = incl;
    __syncthreads();
    int wexcl = 0;
    #pragma unroll
    for (int j = 0; j < 8; j++) wexcl += (j < w) ? ws[j] : 0;
    int run = boff[b] + wexcl + (incl - tsum);
    #pragma unroll
    for (int j = 0; j < 4; j++) {
        if (base + j < NTOT) ptr[base + j] = run;
        run += d[j];
    }
}

__global__ void fill_kernel(const int* __restrict__ edge_ui, const int* __restrict__ edge_iu,
                            const int* __restrict__ ptr, int* __restrict__ cur,
                            int* __restrict__ col) {
    int i = blockIdx.x * blockDim.x + threadIdx.x;
    if (i < NEDGE) {
        int d = __ldg(edge_iu + NEDGE + i);
        int p = atomicAdd(&cur[d], 1);
        col[__ldg(ptr + d) + p] = __ldg(edge_iu + i);
    } else if (i < 2 * NEDGE) {
        int e = i - NEDGE;
        int d = NUSER + __ldg(edge_ui + NEDGE + e);
        int p = atomicAdd(&cur[d], 1);
        col[__ldg(ptr + d) + p] = __ldg(edge_ui + e);
    }
}

// ---------------- TF32 mma GEMM, cp.async 2-stage, concatenated N with split output --------
// C0[M,SPLIT] = A[M,K] @ W0[K,SPLIT]  (+bias,ReLU when BIASRELU)
// C1[M,BN-SPLIT] = A[M,K] @ W1[K,BN-SPLIT]            (only when SPLIT < BN)
// Tile: 128 x BN per CTA, 256 threads, 8 warps (2 in M x 4 in N), WM=64, WN=BN/4.
template<int BN, int SPLIT, bool BIASRELU>
__global__ void __launch_bounds__(256)
gemm_kernel(const float* __restrict__ A,
            const float* __restrict__ W0, const float* __restrict__ W1,
            const float* __restrict__ bias,
            float* __restrict__ C0, float* __restrict__ C1,
            int M, int K)
{
    constexpr int WN = BN / 4;
    constexpr int MT = 4;          // 64 / 16
    constexpr int NT = WN / 8;
    constexpr int BROW = BN + 8;   // Bs row stride (floats)
    constexpr int A_ST = 128 * 36; // floats per A stage
    constexpr int B_ST = 32 * BROW;
    constexpr int STG  = A_ST + B_ST;

    extern __shared__ float sm[];
    const uint32_t smb = smem_u32(sm);

    const int t = threadIdx.x;
    const int w = t >> 5, lane = t & 31;
    const int g = lane >> 2, tg = lane & 3;
    const int wm = w >> 2, wn = w & 3;
    const int m0 = blockIdx.x * 128;
    const int CH = K >> 5;

    float acc[MT][NT][4];
    #pragma unroll
    for (int mt = 0; mt < MT; mt++)
        #pragma unroll
        for (int nt = 0; nt < NT; nt++)
            #pragma unroll
            for (int j = 0; j < 4; j++) acc[mt][nt][j] = 0.f;

    // ---- async tile loaders ----
    auto loadA = [&](int c, int buf) {
        uint32_t base = smb + (uint32_t)(buf * STG) * 4u;
        #pragma unroll
        for (int q = 0; q < 4; q++) {
            int i = t + q * 256;          // 1024 16B-chunks
            int row = i >> 3, j = i & 7;
            bool val = (m0 + row) < M;
            const float* src = val ? (A + (size_t)(m0 + row) * K + c * 32 + j * 4) : A;
            cpa16(base + (uint32_t)(row * 36 + j * 4) * 4u, src, val ? 16 : 0);
        }
    };
    auto loadB = [&](int c, int buf) {
        uint32_t base = smb + (uint32_t)(buf * STG + A_ST) * 4u;
        #pragma unroll
        for (int i = t; i < 8 * BN; i += 256) {
            int k = i / (BN / 4);
            int ncol = (i % (BN / 4)) * 4;
            const float* src = (ncol < SPLIT)
                ? (W0 + (size_t)(c * 32 + k) * SPLIT + ncol)
                : (W1 + (size_t)(c * 32 + k) * (BN - SPLIT) + (ncol - SPLIT));
            cpa16(base + (uint32_t)(k * BROW + ncol) * 4u, src, 16);
        }
    };

    loadA(0, 0); loadB(0, 0); cpa_commit();

    for (int c = 0; c < CH; c++) {
        if (c + 1 < CH) {
            loadA(c + 1, (c + 1) & 1); loadB(c + 1, (c + 1) & 1); cpa_commit();
            cpa_wait<1>();
        } else {
            cpa_wait<0>();
        }
        __syncthreads();

        const float* As = sm + (c & 1) * STG;
        const float* Bs = As + A_ST;

        #pragma unroll
        for (int kk = 0; kk < 32; kk += 8) {
            unsigned a[MT][4], b[NT][2];
            #pragma unroll
            for (int mt = 0; mt < MT; mt++) {
                int r = wm * 64 + mt * 16 + g;
                a[mt][0] = f2tf(As[r * 36 + kk + tg]);
                a[mt][1] = f2tf(As[(r + 8) * 36 + kk + tg]);
                a[mt][2] = f2tf(As[r * 36 + kk + tg + 4]);
                a[mt][3] = f2tf(As[(r + 8) * 36 + kk + tg + 4]);
            }
            #pragma unroll
            for (int nt = 0; nt < NT; nt++) {
                int cc = wn * WN + nt * 8 + g;
                b[nt][0] = f2tf(Bs[(kk + tg) * BROW + cc]);
                b[nt][1] = f2tf(Bs[(kk + tg + 4) * BROW + cc]);
            }
            #pragma unroll
            for (int mt = 0; mt < MT; mt++)
                #pragma unroll
                for (int nt = 0; nt < NT; nt++)
                    mma8(acc[mt][nt], a[mt], b[nt]);
        }
        __syncthreads();
    }

    // ---- epilogue: split fragment stores ----
    #pragma unroll
    for (int mt = 0; mt < MT; mt++) {
        int r0 = m0 + wm * 64 + mt * 16 + g;
        #pragma unroll
        for (int nt = 0; nt < NT; nt++) {
            int c = wn * WN + nt * 8 + 2 * tg;
            float x0 = acc[mt][nt][0], x1 = acc[mt][nt][1];
            float x2 = acc[mt][nt][2], x3 = acc[mt][nt][3];
            if (BIASRELU) {
                float b0 = __ldg(bias + c), b1 = __ldg(bias + c + 1);
                x0 = fmaxf(x0 + b0, 0.f); x1 = fmaxf(x1 + b1, 0.f);
                x2 = fmaxf(x2 + b0, 0.f); x3 = fmaxf(x3 + b1, 0.f);
            }
            float* base; int stride, cc;
            if (c < SPLIT) { base = C0; stride = SPLIT; cc = c; }
            else           { base = C1; stride = BN - SPLIT; cc = c - SPLIT; }
            if (r0 < M)
                *reinterpret_cast<float2*>(base + (size_t)r0 * stride + cc) = make_float2(x0, x1);
            if (r0 + 8 < M)
                *reinterpret_cast<float2*>(base + (size_t)(r0 + 8) * stride + cc) = make_float2(x2, x3);
        }
    }
}

// ---------------- fused CSR gather-mean + self + bias + LN (+ReLU) ----------------
// one warp per destination node; VPL floats per lane (C = 32*VPL); simple loop (low MLP)
template<int VPL, bool RELU>
__global__ void aggfin_kernel(const float* __restrict__ msg, const float* __restrict__ self,
                              const int* __restrict__ ptr, const int* __restrict__ col,
                              const float* __restrict__ bias,
                              const float* __restrict__ gamma, const float* __restrict__ beta,
                              float* __restrict__ out, int n)
{
    constexpr int C = 32 * VPL;
    int gw = (blockIdx.x * blockDim.x + threadIdx.x) >> 5;
    if (gw >= n) return;
    int lane = threadIdx.x & 31;

    int p0 = __ldg(ptr + gw), p1 = __ldg(ptr + gw + 1);
    float v[VPL];
    #pragma unroll
    for (int j = 0; j < VPL; j++) v[j] = 0.f;

    for (int e = p0; e < p1; e++) {
        int s = __ldg(col + e);
        const float* mp = msg + (size_t)s * C + lane * VPL;
        if (VPL == 4) {
            float4 t4 = *reinterpret_cast<const float4*>(mp);
            v[0] += t4.x; v[1] += t4.y; v[2 % VPL] += t4.z; v[3 % VPL] += t4.w;
        } else {
            float2 t2 = *reinterpret_cast<const float2*>(mp);
            v[0] += t2.x; v[1 % VPL] += t2.y;
        }
    }
    float inv = 1.f / fmaxf((float)(p1 - p0), 1.f);

    const float* sp = self + (size_t)gw * C + lane * VPL;
    if (VPL == 4) {
        float4 s4 = *reinterpret_cast<const float4*>(sp);
        v[0] = v[0] * inv + s4.x; v[1] = v[1] * inv + s4.y;
        v[2 % VPL] = v[2 % VPL] * inv + s4.z; v[3 % VPL] = v[3 % VPL] * inv + s4.w;
    } else {
        float2 s2 = *reinterpret_cast<const float2*>(sp);
        v[0] = v[0] * inv + s2.x; v[1 % VPL] = v[1 % VPL] * inv + s2.y;
    }
    #pragma unroll
    for (int j = 0; j < VPL; j++) v[j] += __ldg(bias + lane * VPL + j);

    float s = 0.f;
    #pragma unroll
    for (int j = 0; j < VPL; j++) s += v[j];
    #pragma unroll
    for (int o = 16; o > 0; o >>= 1) s += __shfl_xor_sync(0xffffffffu, s, o);
    float mean = s * (1.f / C);
    float q = 0.f;
    #pragma unroll
    for (int j = 0; j < VPL; j++) { float d = v[j] - mean; q += d * d; }
    #pragma unroll
    for (int o = 16; o > 0; o >>= 1) q += __shfl_xor_sync(0xffffffffu, q, o);
    float rstd = rsqrtf(q * (1.f / C) + LN_EPS);

    float* op = out + (size_t)gw * C + lane * VPL;
    float ov[VPL];
    #pragma unroll
    for (int j = 0; j < VPL; j++) {
        float x = (v[j] - mean) * rstd * __ldg(gamma + lane * VPL + j) + __ldg(beta + lane * VPL + j);
        ov[j] = RELU ? fmaxf(x, 0.f) : x;
    }
    if (VPL == 4)
        *reinterpret_cast<float4*>(op) = make_float4(ov[0], ov[1], ov[2 % VPL], ov[3 % VPL]);
    else
        *reinterpret_cast<float2*>(op) = make_float2(ov[0], ov[1 % VPL]);
}

// ---------------- host ----------------
extern "C" void kernel_launch(void* const* d_in, const int* in_sizes, int n_in,
                              void* d_out, int out_size) {
    (void)in_sizes; (void)n_in; (void)out_size;

    const float* x_user  = (const float*)d_in[0];
    const float* x_item  = (const float*)d_in[1];
    const int*   edge_ui = (const int*)d_in[2];
    const int*   edge_iu = (const int*)d_in[3];
    const float* Wp_u   = (const float*)d_in[4];
    const float* bp_u   = (const float*)d_in[5];
    const float* Wp_i   = (const float*)d_in[6];
    const float* bp_i   = (const float*)d_in[7];
    const float* Wl0_ui = (const float*)d_in[8];
    const float* bl0_ui = (const float*)d_in[9];
    const float* Wr0_ui = (const float*)d_in[10];
    const float* Wl0_iu = (const float*)d_in[11];
    const float* bl0_iu = (const float*)d_in[12];
    const float* Wr0_iu = (const float*)d_in[13];
    const float* g0_u   = (const float*)d_in[14];
    const float* b0_u   = (const float*)d_in[15];
    const float* g0_i   = (const float*)d_in[16];
    const float* b0_i   = (const float*)d_in[17];
    const float* Wl1_ui = (const float*)d_in[18];
    const float* bl1_ui = (const float*)d_in[19];
    const float* Wr1_ui = (const float*)d_in[20];
    const float* Wl1_iu = (const float*)d_in[21];
    const float* bl1_iu = (const float*)d_in[22];
    const float* Wr1_iu = (const float*)d_in[23];
    const float* g1_u   = (const float*)d_in[24];
    const float* b1_u   = (const float*)d_in[25];
    const float* g1_i   = (const float*)d_in[26];
    const float* b1_i   = (const float*)d_in[27];

    float* out = (float*)d_out;
    float* out_u = out;
    float* out_i = out + (size_t)NUSER * 64;

    float *hu, *hi, *Mu, *Qu, *Mi, *Qi;
    int *deg, *cur, *ptr, *col, *bsum, *boff;
    cudaGetSymbolAddress((void**)&hu, g_hu);
    cudaGetSymbolAddress((void**)&hi, g_hi);
    cudaGetSymbolAddress((void**)&Mu, g_Mu);
    cudaGetSymbolAddress((void**)&Qu, g_Qu);
    cudaGetSymbolAddress((void**)&Mi, g_Mi);
    cudaGetSymbolAddress((void**)&Qi, g_Qi);
    cudaGetSymbolAddress((void**)&deg, g_deg);
    cudaGetSymbolAddress((void**)&cur, g_cur);
    cudaGetSymbolAddress((void**)&ptr, g_ptr);
    cudaGetSymbolAddress((void**)&col, g_col);
    cudaGetSymbolAddress((void**)&bsum, g_bsum);
    cudaGetSymbolAddress((void**)&boff, g_boff);

    const int* ptr_u = ptr;
    const int* ptr_i = ptr + NUSER;

    // dynamic smem: 2 stages of (A: 128*36 + B: 32*(BN+8)) floats
    const int smem128 = 2 * (128 * 36 + 32 * (128 + 8)) * 4;   //  71680 B
    const int smem256 = 2 * (128 * 36 + 32 * (256 + 8)) * 4;   // 104448 B
    cudaFuncSetAttribute(gemm_kernel<128, 128, true>,  cudaFuncAttributeMaxDynamicSharedMemorySize, smem128);
    cudaFuncSetAttribute(gemm_kernel<256, 128, false>, cudaFuncAttributeMaxDynamicSharedMemorySize, smem256);
    cudaFuncSetAttribute(gemm_kernel<128, 64,  false>, cudaFuncAttributeMaxDynamicSharedMemorySize, smem128);

    const int e2g = (2 * NEDGE + 255) / 256;
    const int zg  = (NTOT + 255) / 256;
    const int gm  = (NUSER + 127) / 128;
    const int ag  = (NUSER * 32 + 255) / 256;

    // ---- CSR build ----
    zero_kernel<<<zg, 256>>>(deg, cur);
    hist_kernel<<<e2g, 256>>>(edge_ui, edge_iu, deg);
    scan1_kernel<<<SCAN_BLK, 256>>>(deg, bsum);
    scan2_kernel<<<1, 256>>>(bsum, boff, ptr);
    scan3_kernel<<<SCAN_BLK, 256>>>(deg, boff, ptr);
    fill_kernel<<<e2g, 256>>>(edge_ui, edge_iu, ptr, cur, col);

    // ---- input projections + ReLU ----
    gemm_kernel<128, 128, true><<<gm, 256, smem128>>>(x_user, Wp_u, Wp_u, bp_u, hu, hu, NUSER, 96);
    gemm_kernel<128, 128, true><<<gm, 256, smem128>>>(x_item, Wp_i, Wp_i, bp_i, hi, hi, NITEM, 160);

    // ---- layer 0: concatenated source-side GEMMs (N=256, split 128/128) ----
    gemm_kernel<256, 128, false><<<gm, 256, smem256>>>(hu, Wl0_ui, Wr0_iu, nullptr, Mu, Qu, NUSER, 128);
    gemm_kernel<256, 128, false><<<gm, 256, smem256>>>(hi, Wl0_iu, Wr0_ui, nullptr, Mi, Qi, NITEM, 128);

    aggfin_kernel<4, true><<<ag, 256>>>(Mu, Qi, ptr_i, col, bl0_ui, g0_i, b0_i, hi, NITEM);
    aggfin_kernel<4, true><<<ag, 256>>>(Mi, Qu, ptr_u, col, bl0_iu, g0_u, b0_u, hu, NUSER);

    // ---- layer 1: concatenated source-side GEMMs (N=128, split 64/64) ----
    gemm_kernel<128, 64, false><<<gm, 256, smem128>>>(hu, Wl1_ui, Wr1_iu, nullptr, Mu, Qu, NUSER, 128);
    gemm_kernel<128, 64, false><<<gm, 256, smem128>>>(hi, Wl1_iu, Wr1_ui, nullptr, Mi, Qi, NITEM, 128);

    aggfin_kernel<2, false><<<ag, 256>>>(Mu, Qi, ptr_i, col, bl1_ui, g1_i, b1_i, out_i, NITEM);
    aggfin_kernel<2, false><<<ag, 256>>>(Mi, Qu, ptr_u, col, bl1_iu, g1_u, b1_u, out_u, NUSER);
}

// round 15
// speedup vs baseline: 1.5215x; 1.0289x over previous
#include <cuda_runtime.h>
#include <cstddef>
#include <cstdint>

#define NUSER 100000
#define NITEM 100000
#define NEDGE 600000
#define NTOT  (NUSER + NITEM)
#define HDIM  128
#define LN_EPS 1e-5f

// ---------------- scratch (device globals; no allocation allowed) ----------------
__device__ __align__(128) float g_hu [(size_t)NUSER * HDIM];
__device__ __align__(128) float g_hi [(size_t)NITEM * HDIM];
__device__ __align__(128) float g_Mu [(size_t)NUSER * HDIM];
__device__ __align__(128) float g_Qu [(size_t)NUSER * HDIM];
__device__ __align__(128) float g_Mi [(size_t)NITEM * HDIM];
__device__ __align__(128) float g_Qi [(size_t)NITEM * HDIM];
__device__ __align__(128) float g_W  [131072];     // all 10 weights, tf32-pre-rounded, original [K][N] layout

__device__ int g_deg[NTOT];
__device__ int g_cur[NTOT];
__device__ int g_ptr[NTOT + 1];
__device__ int g_col[2 * NEDGE];
__device__ int g_bsum[256];
__device__ int g_boff[256];

#define SCAN_BLK 196

// pre-rounded weight offsets (floats): Wp_u, Wp_i, Wl0_ui, Wr0_iu, Wl0_iu, Wr0_ui, Wl1_ui, Wr1_iu, Wl1_iu, Wr1_ui
#define WO0 0
#define WO1 12288
#define WO2 32768
#define WO3 49152
#define WO4 65536
#define WO5 81920
#define WO6 98304
#define WO7 106496
#define WO8 114688
#define WO9 122880

// ---------------- small helpers ----------------
__device__ __forceinline__ unsigned f2tf(float x) {
    unsigned r;
    asm("cvt.rna.tf32.f32 %0, %1;" : "=r"(r) : "f"(x));
    return r;
}
__device__ __forceinline__ float roundtf(float x) { return __uint_as_float(f2tf(x)); }

__device__ __forceinline__ void mma8(float* c, const unsigned* a, const unsigned* b) {
    asm volatile(
        "mma.sync.aligned.m16n8k8.row.col.f32.tf32.tf32.f32 "
        "{%0,%1,%2,%3}, {%4,%5,%6,%7}, {%8,%9}, {%0,%1,%2,%3};"
        : "+f"(c[0]), "+f"(c[1]), "+f"(c[2]), "+f"(c[3])
        : "r"(a[0]), "r"(a[1]), "r"(a[2]), "r"(a[3]), "r"(b[0]), "r"(b[1]));
}
__device__ __forceinline__ uint32_t smem_u32(const void* p) {
    uint32_t a;
    asm("{ .reg .u64 t; cvta.to.shared.u64 t, %1; cvt.u32.u64 %0, t; }" : "=r"(a) : "l"(p));
    return a;
}
__device__ __forceinline__ void cpa16(uint32_t dst, const void* src, int src_sz) {
    asm volatile("cp.async.cg.shared.global [%0], [%1], 16, %2;"
                 :: "r"(dst), "l"(src), "r"(src_sz));
}
__device__ __forceinline__ void cpa_commit() {
    asm volatile("cp.async.commit_group;" ::: "memory");
}
template<int N>
__device__ __forceinline__ void cpa_wait() {
    asm volatile("cp.async.wait_group %0;" :: "n"(N) : "memory");
}

// ---------------- weight pre-round: out[i] = tf32_round(in[i]) ----------------
struct WPack {
    const float* s[10];
    int off[10];
    int n[10];
};
__global__ void wround_kernel(WPack p, float* __restrict__ wout) {
    int w = blockIdx.y;
    int i = blockIdx.x * 256 + threadIdx.x;
    if (i < p.n[w]) wout[p.off[w] + i] = roundtf(__ldg(p.s[w] + i));
}

// ---------------- CSR build ----------------
__global__ void zero_kernel(int* __restrict__ deg, int* __restrict__ cur) {
    int i = blockIdx.x * blockDim.x + threadIdx.x;
    if (i < NTOT) { deg[i] = 0; cur[i] = 0; }
}

__global__ void hist_kernel(const int* __restrict__ edge_ui, const int* __restrict__ edge_iu,
                            int* __restrict__ deg) {
    int i = blockIdx.x * blockDim.x + threadIdx.x;
    if (i < NEDGE) {
        atomicAdd(&deg[__ldg(edge_iu + NEDGE + i)], 1);
    } else if (i < 2 * NEDGE) {
        atomicAdd(&deg[NUSER + __ldg(edge_ui + NEDGE + (i - NEDGE))], 1);
    }
}

__global__ void scan1_kernel(const int* __restrict__ deg, int* __restrict__ bsum) {
    __shared__ int s[8];
    int b = blockIdx.x;
    int base = b * 1024 + threadIdx.x * 4;
    int sum = 0;
    if (base + 3 < NTOT) {
        int4 v = *reinterpret_cast<const int4*>(deg + base);
        sum = v.x + v.y + v.z + v.w;
    } else {
        for (int j = 0; j < 4; j++) if (base + j < NTOT) sum += deg[base + j];
    }
    #pragma unroll
    for (int o = 16; o; o >>= 1) sum += __shfl_xor_sync(0xffffffffu, sum, o);
    if ((threadIdx.x & 31) == 0) s[threadIdx.x >> 5] = sum;
    __syncthreads();
    if (threadIdx.x == 0) {
        int t = 0;
        #pragma unroll
        for (int j = 0; j < 8; j++) t += s[j];
        bsum[b] = t;
    }
}

__global__ void scan2_kernel(const int* __restrict__ bsum, int* __restrict__ boff,
                             int* __restrict__ ptr) {
    __shared__ int s[256];
    int t = threadIdx.x;
    int v = (t < SCAN_BLK) ? bsum[t] : 0;
    s[t] = v;
    __syncthreads();
    for (int off = 1; off < 256; off <<= 1) {
        int u = (t >= off) ? s[t - off] : 0;
        __syncthreads();
        s[t] += u;
        __syncthreads();
    }
    if (t < SCAN_BLK) boff[t] = s[t] - v;
    if (t == 0) ptr[NTOT] = 2 * NEDGE;
}

__global__ void scan3_kernel(const int* __restrict__ deg, const int* __restrict__ boff,
                             int* __restrict__ ptr) {
    __shared__ int ws[8];
    int b = blockIdx.x;
    int t = threadIdx.x;
    int lane = t & 31, w = t >> 5;
    int base = b * 1024 + t * 4;

    int d[4];
    #pragma unroll
    for (int j = 0; j < 4; j++) d[j] = (base + j < NTOT) ? deg[base + j] : 0;
    int tsum = d[0] + d[1] + d[2] + d[3];

    int incl = tsum;
    #pragma unroll
    for (int o = 1; o < 32; o <<= 1) {
        int u = __shfl_up_sync(0xffffffffu, incl, o);
        if (lane >= o) incl += u;
    }
    if (lane == 31) ws[w] = incl;
    __syncthreads();
    int wexcl = 0;
    #pragma unroll
    for (int j = 0; j < 8; j++) wexcl += (j < w) ? ws[j] : 0;
    int run = boff[b] + wexcl + (incl - tsum);
    #pragma unroll
    for (int j = 0; j < 4; j++) {
        if (base + j < NTOT) ptr[base + j] = run;
        run += d[j];
    }
}

__global__ void fill_kernel(const int* __restrict__ edge_ui, const int* __restrict__ edge_iu,
                            const int* __restrict__ ptr, int* __restrict__ cur,
                            int* __restrict__ col) {
    int i = blockIdx.x * blockDim.x + threadIdx.x;
    if (i < NEDGE) {
        int d = __ldg(edge_iu + NEDGE + i);
        int p = atomicAdd(&cur[d], 1);
        col[__ldg(ptr + d) + p] = __ldg(edge_iu + i);
    } else if (i < 2 * NEDGE) {
        int e = i - NEDGE;
        int d = NUSER + __ldg(edge_ui + NEDGE + e);
        int p = atomicAdd(&cur[d], 1);
        col[__ldg(ptr + d) + p] = __ldg(edge_ui + e);
    }
}

// ---------------- TF32 mma GEMM, cp.async 2-stage, concatenated N with split output --------
// B operands MUST be tf32-pre-rounded. A is pre-rounded unless CVT_A.
// When BIASRELU (projection), output is stored tf32-pre-rounded (it feeds the next GEMM).
template<int BN, int SPLIT, bool BIASRELU, bool CVT_A>
__global__ void __launch_bounds__(256)
gemm_kernel(const float* __restrict__ A,
            const float* __restrict__ W0, const float* __restrict__ W1,
            const float* __restrict__ bias,
            float* __restrict__ C0, float* __restrict__ C1,
            int M, int K)
{
    constexpr int WN = BN / 4;
    constexpr int MT = 4;          // 64 / 16
    constexpr int NT = WN / 8;
    constexpr int BROW = BN + 8;   // Bs row stride (floats)
    constexpr int A_ST = 128 * 36; // floats per A stage
    constexpr int B_ST = 32 * BROW;
    constexpr int STG  = A_ST + B_ST;

    extern __shared__ float sm[];
    const uint32_t smb = smem_u32(sm);

    const int t = threadIdx.x;
    const int w = t >> 5, lane = t & 31;
    const int g = lane >> 2, tg = lane & 3;
    const int wm = w >> 2, wn = w & 3;
    const int m0 = blockIdx.x * 128;
    const int CH = K >> 5;

    float acc[MT][NT][4];
    #pragma unroll
    for (int mt = 0; mt < MT; mt++)
        #pragma unroll
        for (int nt = 0; nt < NT; nt++)
            #pragma unroll
            for (int j = 0; j < 4; j++) acc[mt][nt][j] = 0.f;

    // ---- async tile loaders ----
    auto loadA = [&](int c, int buf) {
        uint32_t base = smb + (uint32_t)(buf * STG) * 4u;
        #pragma unroll
        for (int q = 0; q < 4; q++) {
            int i = t + q * 256;          // 1024 16B-chunks
            int row = i >> 3, j = i & 7;
            bool val = (m0 + row) < M;
            const float* src = val ? (A + (size_t)(m0 + row) * K + c * 32 + j * 4) : A;
            cpa16(base + (uint32_t)(row * 36 + j * 4) * 4u, src, val ? 16 : 0);
        }
    };
    auto loadB = [&](int c, int buf) {
        uint32_t base = smb + (uint32_t)(buf * STG + A_ST) * 4u;
        #pragma unroll
        for (int i = t; i < 8 * BN; i += 256) {
            int k = i / (BN / 4);
            int ncol = (i % (BN / 4)) * 4;
            const float* src = (ncol < SPLIT)
                ? (W0 + (size_t)(c * 32 + k) * SPLIT + ncol)
                : (W1 + (size_t)(c * 32 + k) * (BN - SPLIT) + (ncol - SPLIT));
            cpa16(base + (uint32_t)(k * BROW + ncol) * 4u, src, 16);
        }
    };

    loadA(0, 0); loadB(0, 0); cpa_commit();

    for (int c = 0; c < CH; c++) {
        if (c + 1 < CH) {
            loadA(c + 1, (c + 1) & 1); loadB(c + 1, (c + 1) & 1); cpa_commit();
            cpa_wait<1>();
        } else {
            cpa_wait<0>();
        }
        __syncthreads();

        const float* As = sm + (c & 1) * STG;
        const unsigned* Asu = reinterpret_cast<const unsigned*>(As);
        const unsigned* Bsu = reinterpret_cast<const unsigned*>(As + A_ST);

        #pragma unroll
        for (int kk = 0; kk < 32; kk += 8) {
            unsigned a[MT][4], b[NT][2];
            #pragma unroll
            for (int mt = 0; mt < MT; mt++) {
                int r = wm * 64 + mt * 16 + g;
                if (CVT_A) {
                    a[mt][0] = f2tf(As[r * 36 + kk + tg]);
                    a[mt][1] = f2tf(As[(r + 8) * 36 + kk + tg]);
                    a[mt][2] = f2tf(As[r * 36 + kk + tg + 4]);
                    a[mt][3] = f2tf(As[(r + 8) * 36 + kk + tg + 4]);
                } else {
                    a[mt][0] = Asu[r * 36 + kk + tg];
                    a[mt][1] = Asu[(r + 8) * 36 + kk + tg];
                    a[mt][2] = Asu[r * 36 + kk + tg + 4];
                    a[mt][3] = Asu[(r + 8) * 36 + kk + tg + 4];
                }
            }
            #pragma unroll
            for (int nt = 0; nt < NT; nt++) {
                int cc = wn * WN + nt * 8 + g;
                b[nt][0] = Bsu[(kk + tg) * BROW + cc];
                b[nt][1] = Bsu[(kk + tg + 4) * BROW + cc];
            }
            #pragma unroll
            for (int mt = 0; mt < MT; mt++)
                #pragma unroll
                for (int nt = 0; nt < NT; nt++)
                    mma8(acc[mt][nt], a[mt], b[nt]);
        }
        __syncthreads();
    }

    // ---- epilogue: split fragment stores ----
    #pragma unroll
    for (int mt = 0; mt < MT; mt++) {
        int r0 = m0 + wm * 64 + mt * 16 + g;
        #pragma unroll
        for (int nt = 0; nt < NT; nt++) {
            int c = wn * WN + nt * 8 + 2 * tg;
            float x0 = acc[mt][nt][0], x1 = acc[mt][nt][1];
            float x2 = acc[mt][nt][2], x3 = acc[mt][nt][3];
            if (BIASRELU) {
                float b0 = __ldg(bias + c), b1 = __ldg(bias + c + 1);
                // output feeds the next GEMM's A-operand: store tf32-pre-rounded
                x0 = roundtf(fmaxf(x0 + b0, 0.f)); x1 = roundtf(fmaxf(x1 + b1, 0.f));
                x2 = roundtf(fmaxf(x2 + b0, 0.f)); x3 = roundtf(fmaxf(x3 + b1, 0.f));
            }
            float* base; int stride, cc;
            if (c < SPLIT) { base = C0; stride = SPLIT; cc = c; }
            else           { base = C1; stride = BN - SPLIT; cc = c - SPLIT; }
            if (r0 < M)
                *reinterpret_cast<float2*>(base + (size_t)r0 * stride + cc) = make_float2(x0, x1);
            if (r0 + 8 < M)
                *reinterpret_cast<float2*>(base + (size_t)(r0 + 8) * stride + cc) = make_float2(x2, x3);
        }
    }
}

// ---------------- fused CSR gather-mean + self + bias + LN (+ReLU) ----------------
// one warp per destination node; VPL floats per lane (C = 32*VPL); simple loop (low MLP)
// RELU variant feeds the next GEMM -> outputs stored tf32-pre-rounded.
template<int VPL, bool RELU>
__global__ void aggfin_kernel(const float* __restrict__ msg, const float* __restrict__ self,
                              const int* __restrict__ ptr, const int* __restrict__ col,
                              const float* __restrict__ bias,
                              const float* __restrict__ gamma, const float* __restrict__ beta,
                              float* __restrict__ out, int n)
{
    constexpr int C = 32 * VPL;
    int gw = (blockIdx.x * blockDim.x + threadIdx.x) >> 5;
    if (gw >= n) return;
    int lane = threadIdx.x & 31;

    int p0 = __ldg(ptr + gw), p1 = __ldg(ptr + gw + 1);
    float v[VPL];
    #pragma unroll
    for (int j = 0; j < VPL; j++) v[j] = 0.f;

    for (int e = p0; e < p1; e++) {
        int s = __ldg(col + e);
        const float* mp = msg + (size_t)s * C + lane * VPL;
        if (VPL == 4) {
            float4 t4 = *reinterpret_cast<const float4*>(mp);
            v[0] += t4.x; v[1] += t4.y; v[2 % VPL] += t4.z; v[3 % VPL] += t4.w;
        } else {
            float2 t2 = *reinterpret_cast<const float2*>(mp);
            v[0] += t2.x; v[1 % VPL] += t2.y;
        }
    }
    float inv = 1.f / fmaxf((float)(p1 - p0), 1.f);

    const float* sp = self + (size_t)gw * C + lane * VPL;
    if (VPL == 4) {
        float4 s4 = *reinterpret_cast<const float4*>(sp);
        v[0] = v[0] * inv + s4.x; v[1] = v[1] * inv + s4.y;
        v[2 % VPL] = v[2 % VPL] * inv + s4.z; v[3 % VPL] = v[3 % VPL] * inv + s4.w;
    } else {
        float2 s2 = *reinterpret_cast<const float2*>(sp);
        v[0] = v[0] * inv + s2.x; v[1 % VPL] = v[1 % VPL] * inv + s2.y;
    }
    #pragma unroll
    for (int j = 0; j < VPL; j++) v[j] += __ldg(bias + lane * VPL + j);

    float s = 0.f;
    #pragma unroll
    for (int j = 0; j < VPL; j++) s += v[j];
    #pragma unroll
    for (int o = 16; o > 0; o >>= 1) s += __shfl_xor_sync(0xffffffffu, s, o);
    float mean = s * (1.f / C);
    float q = 0.f;
    #pragma unroll
    for (int j = 0; j < VPL; j++) { float d = v[j] - mean; q += d * d; }
    #pragma unroll
    for (int o = 16; o > 0; o >>= 1) q += __shfl_xor_sync(0xffffffffu, q, o);
    float rstd = rsqrtf(q * (1.f / C) + LN_EPS);

    float* op = out + (size_t)gw * C + lane * VPL;
    float ov[VPL];
    #pragma unroll
    for (int j = 0; j < VPL; j++) {
        float x = (v[j] - mean) * rstd * __ldg(gamma + lane * VPL + j) + __ldg(beta + lane * VPL + j);
        ov[j] = RELU ? roundtf(fmaxf(x, 0.f)) : x;
    }
    if (VPL == 4)
        *reinterpret_cast<float4*>(op) = make_float4(ov[0], ov[1], ov[2 % VPL], ov[3 % VPL]);
    else
        *reinterpret_cast<float2*>(op) = make_float2(ov[0], ov[1 % VPL]);
}

// ---------------- host ----------------
extern "C" void kernel_launch(void* const* d_in, const int* in_sizes, int n_in,
                              void* d_out, int out_size) {
    (void)in_sizes; (void)n_in; (void)out_size;

    const float* x_user  = (const float*)d_in[0];
    const float* x_item  = (const float*)d_in[1];
    const int*   edge_ui = (const int*)d_in[2];
    const int*   edge_iu = (const int*)d_in[3];
    const float* Wp_u   = (const float*)d_in[4];
    const float* bp_u   = (const float*)d_in[5];
    const float* Wp_i   = (const float*)d_in[6];
    const float* bp_i   = (const float*)d_in[7];
    const float* Wl0_ui = (const float*)d_in[8];
    const float* bl0_ui = (const float*)d_in[9];
    const float* Wr0_ui = (const float*)d_in[10];
    const float* Wl0_iu = (const float*)d_in[11];
    const float* bl0_iu = (const float*)d_in[12];
    const float* Wr0_iu = (const float*)d_in[13];
    const float* g0_u   = (const float*)d_in[14];
    const float* b0_u   = (const float*)d_in[15];
    const float* g0_i   = (const float*)d_in[16];
    const float* b0_i   = (const float*)d_in[17];
    const float* Wl1_ui = (const float*)d_in[18];
    const float* bl1_ui = (const float*)d_in[19];
    const float* Wr1_ui = (const float*)d_in[20];
    const float* Wl1_iu = (const float*)d_in[21];
    const float* bl1_iu = (const float*)d_in[22];
    const float* Wr1_iu = (const float*)d_in[23];
    const float* g1_u   = (const float*)d_in[24];
    const float* b1_u   = (const float*)d_in[25];
    const float* g1_i   = (const float*)d_in[26];
    const float* b1_i   = (const float*)d_in[27];

    float* out = (float*)d_out;
    float* out_u = out;
    float* out_i = out + (size_t)NUSER * 64;

    float *hu, *hi, *Mu, *Qu, *Mi, *Qi, *wr;
    int *deg, *cur, *ptr, *col, *bsum, *boff;
    cudaGetSymbolAddress((void**)&hu, g_hu);
    cudaGetSymbolAddress((void**)&hi, g_hi);
    cudaGetSymbolAddress((void**)&Mu, g_Mu);
    cudaGetSymbolAddress((void**)&Qu, g_Qu);
    cudaGetSymbolAddress((void**)&Mi, g_Mi);
    cudaGetSymbolAddress((void**)&Qi, g_Qi);
    cudaGetSymbolAddress((void**)&wr, g_W);
    cudaGetSymbolAddress((void**)&deg, g_deg);
    cudaGetSymbolAddress((void**)&cur, g_cur);
    cudaGetSymbolAddress((void**)&ptr, g_ptr);
    cudaGetSymbolAddress((void**)&col, g_col);
    cudaGetSymbolAddress((void**)&bsum, g_bsum);
    cudaGetSymbolAddress((void**)&boff, g_boff);

    const int* ptr_u = ptr;
    const int* ptr_i = ptr + NUSER;

    // dynamic smem: 2 stages of (A: 128*36 + B: 32*(BN+8)) floats
    const int smem128 = 2 * (128 * 36 + 32 * (128 + 8)) * 4;   //  71680 B
    const int smem256 = 2 * (128 * 36 + 32 * (256 + 8)) * 4;   // 104448 B
    cudaFuncSetAttribute(gemm_kernel<128, 128, true,  true>,  cudaFuncAttributeMaxDynamicSharedMemorySize, smem128);
    cudaFuncSetAttribute(gemm_kernel<256, 128, false, false>, cudaFuncAttributeMaxDynamicSharedMemorySize, smem256);
    cudaFuncSetAttribute(gemm_kernel<128, 64,  false, false>, cudaFuncAttributeMaxDynamicSharedMemorySize, smem128);

    const int e2g = (2 * NEDGE + 255) / 256;
    const int zg  = (NTOT + 255) / 256;
    const int gm  = (NUSER + 127) / 128;
    const int ag  = (NUSER * 32 + 255) / 256;

    // ---- weight pre-round (one launch, all 10 matrices) ----
    {
        WPack p;
        p.s[0] = Wp_u;   p.off[0] = WO0; p.n[0] = 96 * 128;
        p.s[1] = Wp_i;   p.off[1] = WO1; p.n[1] = 160 * 128;
        p.s[2] = Wl0_ui; p.off[2] = WO2; p.n[2] = 128 * 128;
        p.s[3] = Wr0_iu; p.off[3] = WO3; p.n[3] = 128 * 128;
        p.s[4] = Wl0_iu; p.off[4] = WO4; p.n[4] = 128 * 128;
        p.s[5] = Wr0_ui; p.off[5] = WO5; p.n[5] = 128 * 128;
        p.s[6] = Wl1_ui; p.off[6] = WO6; p.n[6] = 128 * 64;
        p.s[7] = Wr1_iu; p.off[7] = WO7; p.n[7] = 128 * 64;
        p.s[8] = Wl1_iu; p.off[8] = WO8; p.n[8] = 128 * 64;
        p.s[9] = Wr1_ui; p.off[9] = WO9; p.n[9] = 128 * 64;
        dim3 wg((160 * 128 + 255) / 256, 10);
        wround_kernel<<<wg, 256>>>(p, wr);
    }

    // ---- input projections + ReLU (A needs cvt; output stored pre-rounded) ----
    gemm_kernel<128, 128, true, true><<<gm, 256, smem128>>>(x_user, wr + WO0, wr + WO0, bp_u, hu, hu, NUSER, 96);
    gemm_kernel<128, 128, true, true><<<gm, 256, smem128>>>(x_item, wr + WO1, wr + WO1, bp_i, hi, hi, NITEM, 160);

    // ---- layer 0: concatenated source-side GEMMs (N=256, split 128/128); all operands pre-rounded ----
    gemm_kernel<256, 128, false, false><<<gm, 256, smem256>>>(hu, wr + WO2, wr + WO3, nullptr, Mu, Qu, NUSER, 128);
    gemm_kernel<256, 128, false, false><<<gm, 256, smem256>>>(hi, wr + WO4, wr + WO5, nullptr, Mi, Qi, NITEM, 128);

    // ---- CSR build (moved after GEMMs; only aggfin depends on it) ----
    zero_kernel<<<zg, 256>>>(deg, cur);
    hist_kernel<<<e2g, 256>>>(edge_ui, edge_iu, deg);
    scan1_kernel<<<SCAN_BLK, 256>>>(deg, bsum);
    scan2_kernel<<<1, 256>>>(bsum, boff, ptr);
    scan3_kernel<<<SCAN_BLK, 256>>>(deg, boff, ptr);
    fill_kernel<<<e2g, 256>>>(edge_ui, edge_iu, ptr, cur, col);

    aggfin_kernel<4, true><<<ag, 256>>>(Mu, Qi, ptr_i, col, bl0_ui, g0_i, b0_i, hi, NITEM);
    aggfin_kernel<4, true><<<ag, 256>>>(Mi, Qu, ptr_u, col, bl0_iu, g0_u, b0_u, hu, NUSER);

    // ---- layer 1: concatenated source-side GEMMs (N=128, split 64/64); all operands pre-rounded ----
    gemm_kernel<128, 64, false, false><<<gm, 256, smem128>>>(hu, wr + WO6, wr + WO7, nullptr, Mu, Qu, NUSER, 128);
    gemm_kernel<128, 64, false, false><<<gm, 256, smem128>>>(hi, wr + WO8, wr + WO9, nullptr, Mi, Qi, NITEM, 128);

    aggfin_kernel<2, false><<<ag, 256>>>(Mu, Qi, ptr_i, col, bl1_ui, g1_i, b1_i, out_i, NITEM);
    aggfin_kernel<2, false><<<ag, 256>>>(Mi, Qu, ptr_u, col, bl1_iu, g1_u, b1_u, out_u, NUSER);
}